// round 3
// baseline (speedup 1.0000x reference)
#include <cuda_runtime.h>
#include <math.h>

#define B 32
#define D 512
#define H 1024
#define H3 (3*H)
#define NBLK 148
#define NTHR 256

typedef unsigned long long ull;

// ---------------- persistent device scratch (no allocation allowed) --------
// Activations use a PAIRED layout: feature pairs (2p, 2p+1) stored as float2
// at [p*B + b], so the GEMMs can LDS.64 straight into fma.rn.f32x2 operands.
__device__ __align__(16) float g_Wcomb[H3 * D];   // W_ih @ W_enc  [3H, D]
__device__ __align__(16) float g_bcomb[H3];       // W_ih @ b_enc + b_gru
__device__ __align__(16) float g_x2[D * B];       // input, paired  [(D/2)][B] x float2
__device__ __align__(16) float g_hA[H * B];       // hidden ping, paired
__device__ __align__(16) float g_hB[H * B];       // hidden pong, paired
__device__ unsigned g_arrive;                     // barrier ticket (monotonic)

// ---------------- fast-math-immune precise fp32 transcendentals ------------
__device__ __forceinline__ float exp_acc(float x) {
    x = fminf(fmaxf(x, -80.f), 80.f);
    float t = fmaf(x, 1.4426950408889634f, 12582912.f);
    float k = t - 12582912.f;                       // round(x/ln2)
    float r = fmaf(k, -0.693359375f, x);            // Cody-Waite hi
    r = fmaf(k, 2.12194440054690583e-4f, r);        // Cody-Waite lo
    float p = 1.9841269841e-4f;                     // 1/5040
    p = fmaf(p, r, 1.3888888889e-3f);               // 1/720
    p = fmaf(p, r, 8.3333333333e-3f);               // 1/120
    p = fmaf(p, r, 4.1666666667e-2f);               // 1/24
    p = fmaf(p, r, 1.6666666667e-1f);               // 1/6
    p = fmaf(p, r, 0.5f);
    float y = fmaf(p, r * r, r) + 1.0f;             // e^r, |err| ~ 1 ulp
    int ki = (int)k;
    float s = __int_as_float((ki + 127) << 23);
    return y * s;
}
__device__ __forceinline__ float sigmoid_acc(float x) {
    return __frcp_rn(1.0f + exp_acc(-x));
}
__device__ __forceinline__ float tanh_acc(float x) {
    float ax = fabsf(x);
    float e = exp_acc(2.0f * ax);
    float t = fmaf(-2.0f, __frcp_rn(e + 1.0f), 1.0f);
    return (x < 0.f) ? -t : t;
}

// ---------------- packed f32x2 helpers --------------------------------------
__device__ __forceinline__ void fma2(ull& acc, ull a, ull b) {
    asm("fma.rn.f32x2 %0, %1, %2, %0;" : "+l"(acc) : "l"(a), "l"(b));
}
__device__ __forceinline__ float2 upk(ull u) {
    float a, b;
    asm("mov.b64 {%0, %1}, %2;" : "=f"(a), "=f"(b) : "l"(u));
    return make_float2(a, b);
}

// ---------------- precompute: W_comb = W_ih @ W_enc (Kahan) -----------------
// block = 8 consecutive r rows; 256 threads each own 2 d columns.
__global__ void __launch_bounds__(256) precompute_wcomb(
    const float* __restrict__ W_ih,   // [3H, H]
    const float* __restrict__ W_enc)  // [H, D]
{
    __shared__ float wih[8][H];
    int r0 = blockIdx.x * 8;
    for (int i = threadIdx.x; i < 8 * H; i += 256)
        wih[i >> 10][i & (H - 1)] = W_ih[(size_t)r0 * H + i];
    __syncthreads();

    int d0 = threadIdx.x;
    int d1 = threadIdx.x + 256;
    float s[16], c[16];
    #pragma unroll
    for (int j = 0; j < 16; j++) { s[j] = 0.f; c[j] = 0.f; }

    for (int k = 0; k < H; k++) {
        float e0 = __ldg(&W_enc[(size_t)k * D + d0]);
        float e1 = __ldg(&W_enc[(size_t)k * D + d1]);
        #pragma unroll
        for (int j = 0; j < 8; j++) {
            float w = wih[j][k];
            {   // (j, d0)
                float tp = __fmul_rn(w, e0);
                float y  = __fsub_rn(tp, c[2*j]);
                float s2 = __fadd_rn(s[2*j], y);
                c[2*j]   = __fsub_rn(__fsub_rn(s2, s[2*j]), y);
                s[2*j]   = s2;
            }
            {   // (j, d1)
                float tp = __fmul_rn(w, e1);
                float y  = __fsub_rn(tp, c[2*j+1]);
                float s2 = __fadd_rn(s[2*j+1], y);
                c[2*j+1] = __fsub_rn(__fsub_rn(s2, s[2*j+1]), y);
                s[2*j+1] = s2;
            }
        }
    }
    #pragma unroll
    for (int j = 0; j < 8; j++) {
        g_Wcomb[(size_t)(r0 + j) * D + d0] = s[2*j];
        g_Wcomb[(size_t)(r0 + j) * D + d1] = s[2*j+1];
    }
}

__global__ void precompute_bcomb(
    const float* __restrict__ W_ih,
    const float* __restrict__ b_enc,
    const float* __restrict__ b_gru)
{
    int r = blockIdx.x * blockDim.x + threadIdx.x;
    if (r < H3) {
        const float* wi = W_ih + (size_t)r * H;
        double acc = (double)b_gru[r];
        for (int k = 0; k < H; k++)
            acc += (double)wi[k] * (double)b_enc[k];
        g_bcomb[r] = (float)acc;
    }
}

// ---------------- init: h0 = 0, x paired-transpose of x0 -------------------
__global__ void init_state(const float* __restrict__ x0)  // [B, D]
{
    int i = blockIdx.x * blockDim.x + threadIdx.x;
    if (i < D * B) {
        int b = i / D;
        int d = i - b * D;
        g_x2[((d >> 1) * B + b) * 2 + (d & 1)] = x0[i];
    }
    if (i < H * B) g_hA[i] = 0.f;
}

// ---------------- grid-wide barrier -----------------------------------------
__device__ __forceinline__ void grid_sync() {
    __syncthreads();
    if (threadIdx.x == 0) {
        unsigned ticket;
        asm volatile("atom.add.release.gpu.global.u32 %0, [%1], 1;"
                     : "=r"(ticket) : "l"(&g_arrive) : "memory");
        unsigned n = gridDim.x;
        unsigned target = ticket - (ticket % n) + n;
        unsigned v;
        do {
            asm volatile("ld.acquire.gpu.global.u32 %0, [%1];"
                         : "=r"(v) : "l"(&g_arrive) : "memory");
        } while (v < target);
    }
    __syncthreads();
}

// ---------------- persistent GRU kernel -------------------------------------
__global__ void __launch_bounds__(NTHR, 1) gru_persistent(
    const float* __restrict__ W_hh,   // [3H, H]
    const float* __restrict__ b_n,    // [H]
    const float* __restrict__ W_dec,  // [2D, H]
    const float* __restrict__ b_dec,  // [2D]
    const float* __restrict__ eps,    // [T, B, D]
    float* __restrict__ out,
    int steps)
{
    extern __shared__ float sm[];   // phase A: x(64KB) + h(128KB); phase B: h + partials
    const int tid  = threadIdx.x;
    const int lane = tid & 31;      // batch index
    const int w    = tid >> 5;      // warp in block (0..7)
    const int blk  = blockIdx.x;

    const int j  = w * NBLK + blk;          // gate column (active if < H)
    const int p  = w >> 1;                  // decode pair id (0..3)
    const int kh = w & 1;                   // decode K-half
    const int d  = p * NBLK + blk;          // decode output dim (active if < D)

    const size_t plane = (size_t)steps * (B * D);

    for (int t = 0; t < steps; t++) {
        const float* hin  = (t & 1) ? g_hB : g_hA;
        float*       hout = (t & 1) ? g_hA : g_hB;

        // ---- stage x and h into smem (L2-coherent, bypass L1) ----
        {
            const float4* sx = (const float4*)g_x2;
            float4* dx = (float4*)sm;
            #pragma unroll
            for (int i = tid; i < (D * B) / 4; i += NTHR) dx[i] = __ldcg(sx + i);
            const float4* sh = (const float4*)hin;
            float4* dh = (float4*)(sm + D * B);
            #pragma unroll
            for (int i = tid; i < (H * B) / 4; i += NTHR) dh[i] = __ldcg(sh + i);
        }
        __syncthreads();

        // ---- phase A: gates + GRU update ----
        if (j < H) {
            ull ar2 = 0, az2 = 0, an2 = 0, hn2 = 0;
            // input gates: x (D) vs W_comb rows j, H+j, 2H+j
            {
                const ulonglong2* wr = (const ulonglong2*)(g_Wcomb + (size_t)j * D);
                const ulonglong2* wz = (const ulonglong2*)(g_Wcomb + (size_t)(H + j) * D);
                const ulonglong2* wn = (const ulonglong2*)(g_Wcomb + (size_t)(2 * H + j) * D);
                const ull* xs8 = (const ull*)sm;
                #pragma unroll 4
                for (int k4 = 0; k4 < D / 4; k4++) {
                    ulonglong2 a = wr[k4];
                    ulonglong2 b = wz[k4];
                    ulonglong2 cw = wn[k4];
                    ull x01 = xs8[(2 * k4 + 0) * B + lane];
                    ull x23 = xs8[(2 * k4 + 1) * B + lane];
                    fma2(ar2, a.x, x01);  fma2(ar2, a.y, x23);
                    fma2(az2, b.x, x01);  fma2(az2, b.y, x23);
                    fma2(an2, cw.x, x01); fma2(an2, cw.y, x23);
                }
            }
            // hidden gates: h (H) vs W_hh rows j, H+j, 2H+j
            {
                const ulonglong2* vr = (const ulonglong2*)(W_hh + (size_t)j * H);
                const ulonglong2* vz = (const ulonglong2*)(W_hh + (size_t)(H + j) * H);
                const ulonglong2* vn = (const ulonglong2*)(W_hh + (size_t)(2 * H + j) * H);
                const ull* hs8 = (const ull*)(sm + D * B);
                #pragma unroll 4
                for (int k4 = 0; k4 < H / 4; k4++) {
                    ulonglong2 a = __ldg(&vr[k4]);
                    ulonglong2 b = __ldg(&vz[k4]);
                    ulonglong2 cw = __ldg(&vn[k4]);
                    ull h01 = hs8[(2 * k4 + 0) * B + lane];
                    ull h23 = hs8[(2 * k4 + 1) * B + lane];
                    fma2(ar2, a.x, h01);  fma2(ar2, a.y, h23);
                    fma2(az2, b.x, h01);  fma2(az2, b.y, h23);
                    fma2(hn2, cw.x, h01); fma2(hn2, cw.y, h23);
                }
            }
            float2 u;
            u = upk(ar2); float pr = g_bcomb[j]         + u.x + u.y;
            u = upk(az2); float pz = g_bcomb[H + j]     + u.x + u.y;
            u = upk(an2); float pn = g_bcomb[2 * H + j] + u.x + u.y;
            u = upk(hn2); float hn = u.x + u.y;

            float rg = sigmoid_acc(pr);
            float zg = sigmoid_acc(pz);
            float ng = tanh_acc(fmaf(rg, hn + b_n[j], pn));
            const float* hs = sm + D * B;
            float hp = hs[((j >> 1) * B + lane) * 2 + (j & 1)];
            hout[((j >> 1) * B + lane) * 2 + (j & 1)] = ng + zg * (hp - ng);
        }
        grid_sync();

        // ---- stage h_new into smem ----
        {
            const float4* sh = (const float4*)hout;
            float4* dh = (float4*)sm;
            #pragma unroll
            for (int i = tid; i < (H * B) / 4; i += NTHR) dh[i] = __ldcg(sh + i);
        }
        __syncthreads();

        // ---- phase B: decoder (K split across warp pairs) ----
        float am = 0.f, als = 0.f;
        if (d < D) {
            ull am2 = 0, as2 = 0;
            const ulonglong2* wm = (const ulonglong2*)(W_dec + (size_t)d * H) + kh * (H / 8);
            const ulonglong2* ws = (const ulonglong2*)(W_dec + (size_t)(D + d) * H) + kh * (H / 8);
            const ull* hs8 = (const ull*)sm + kh * (H / 4) * B;   // half = H/2 floats = H/4 pairs
            #pragma unroll 4
            for (int k4 = 0; k4 < H / 8; k4++) {   // 512 k per half
                ulonglong2 a = __ldg(&wm[k4]);
                ulonglong2 b = __ldg(&ws[k4]);
                ull h01 = hs8[(2 * k4 + 0) * B + lane];
                ull h23 = hs8[(2 * k4 + 1) * B + lane];
                fma2(am2, a.x, h01); fma2(am2, a.y, h23);
                fma2(as2, b.x, h01); fma2(as2, b.y, h23);
            }
            float2 u;
            u = upk(am2); am  = u.x + u.y;
            u = upk(as2); als = u.x + u.y;
        }
        float2* part = (float2*)(sm + H * B);   // 4 pairs x 32 lanes
        if (d < D && kh == 1) part[p * B + lane] = make_float2(am, als);
        __syncthreads();
        if (d < D && kh == 0) {
            float2 pp = part[p * B + lane];
            float mu  = am + pp.x + b_dec[d];
            float ls  = als + pp.y + b_dec[D + d];
            float sig = exp_acc(ls);
            size_t o  = (size_t)t * (B * D) + (size_t)lane * D + d;
            float xn  = fmaf(sig, eps[o], mu);
            g_x2[((d >> 1) * B + lane) * 2 + (d & 1)] = xn;   // next input
            out[o]             = xn;    // samples
            out[plane + o]     = mu;    // means
            out[2 * plane + o] = sig;   // sigmas
        }
        grid_sync();
    }
}

// ---------------- launch ----------------------------------------------------
extern "C" void kernel_launch(void* const* d_in, const int* in_sizes, int n_in,
                              void* d_out, int out_size)
{
    const float* x0    = (const float*)d_in[0];
    const float* eps   = (const float*)d_in[1];
    const float* W_enc = (const float*)d_in[2];
    const float* b_enc = (const float*)d_in[3];
    const float* W_ih  = (const float*)d_in[4];
    const float* W_hh  = (const float*)d_in[5];
    const float* b_gru = (const float*)d_in[6];
    const float* b_n   = (const float*)d_in[7];
    const float* W_dec = (const float*)d_in[8];
    const float* b_dec = (const float*)d_in[9];

    int steps = in_sizes[1] / (B * D);   // eps is [T, B, D]
    float* out = (float*)d_out;

    const int smem_bytes = (D + H) * B * sizeof(float);   // 196608
    cudaFuncSetAttribute(gru_persistent,
                         cudaFuncAttributeMaxDynamicSharedMemorySize, smem_bytes);

    precompute_wcomb<<<H3 / 8, 256>>>(W_ih, W_enc);
    precompute_bcomb<<<(H3 + 255) / 256, 256>>>(W_ih, b_enc, b_gru);
    init_state<<<(H * B + 255) / 256, 256>>>(x0);
    gru_persistent<<<NBLK, NTHR, smem_bytes>>>(W_hh, b_n, W_dec, b_dec, eps, out, steps);
}

// round 4
// speedup vs baseline: 1.1487x; 1.1487x over previous
#include <cuda_runtime.h>
#include <math.h>

#define B 32
#define D 512
#define H 1024
#define H3 (3*H)
#define NBLK 128
#define NTHR 256
#define KPX 256            // x feature-pairs
#define KPH 512            // h feature-pairs
#define KPA (KPX+KPH)      // 768 combined feature-pairs (phase A)

typedef unsigned long long ull;

// ---------------- persistent device scratch --------------------------------
__device__ __align__(16) float g_Wcomb[H3 * D];            // temp: W_ih @ W_enc
__device__ float g_bcomb[H3];
// phase A weights, packed: per (blk, kp, col c): ulonglong2{ r-pair, z-pair }
__device__ __align__(16) ulonglong2 g_WArz[NBLK * KPA * 8];      // 25.2 MB
// n-gate pairs: per (blk, kp, colgroup cg): ulonglong2{ n-ull col 2cg, col 2cg+1 }
__device__ __align__(16) ulonglong2 g_WAn [NBLK * KPA * 4];      // 12.6 MB
// decoder: per (blk, kp, dof): ulonglong2{ mu-row pair, logstd-row pair }
__device__ __align__(16) ulonglong2 g_WD  [NBLK * KPH * 4];      // 4 MB
// activations, f32x2 feature-pairs: [kp][batch]; kp<256 = x, kp>=256 = h
__device__ __align__(16) ull g_act[2][KPA * B];                  // 2 x 192 KB
__device__ unsigned g_arrive;

// ---------------- packed f32x2 helpers --------------------------------------
__device__ __forceinline__ void fma2(ull& acc, ull a, ull b) {
    asm("fma.rn.f32x2 %0, %1, %2, %0;" : "+l"(acc) : "l"(a), "l"(b));
}
__device__ __forceinline__ void add2(ull& acc, ull a) {
    asm("add.rn.f32x2 %0, %0, %1;" : "+l"(acc) : "l"(a));
}
__device__ __forceinline__ float2 upk(ull u) {
    float a, b;
    asm("mov.b64 {%0, %1}, %2;" : "=f"(a), "=f"(b) : "l"(u));
    return make_float2(a, b);
}
__device__ __forceinline__ ull packf2(float lo, float hi) {
    ull u; asm("mov.b64 %0, {%1, %2};" : "=l"(u) : "f"(lo), "f"(hi)); return u;
}
__device__ __forceinline__ ulonglong2 ldcg2(const ull* p) {
    ulonglong2 v;
    asm volatile("ld.global.cg.v2.u64 {%0, %1}, [%2];"
                 : "=l"(v.x), "=l"(v.y) : "l"(p));
    return v;
}
__device__ __forceinline__ ulonglong2 ldg2(const ulonglong2* p) {
    ulonglong2 v;
    asm("ld.global.nc.v2.u64 {%0, %1}, [%2];"
        : "=l"(v.x), "=l"(v.y) : "l"(p));
    return v;
}
__device__ __forceinline__ float ldcg_f(const float* p) {
    float v;
    asm volatile("ld.global.cg.f32 %0, [%1];" : "=f"(v) : "l"(p));
    return v;
}

// ---------------- fast-math-immune precise fp32 transcendentals ------------
__device__ __forceinline__ float exp_acc(float x) {
    x = fminf(fmaxf(x, -80.f), 80.f);
    float t = fmaf(x, 1.4426950408889634f, 12582912.f);
    float k = t - 12582912.f;
    float r = fmaf(k, -0.693359375f, x);
    r = fmaf(k, 2.12194440054690583e-4f, r);
    float p = 1.9841269841e-4f;
    p = fmaf(p, r, 1.3888888889e-3f);
    p = fmaf(p, r, 8.3333333333e-3f);
    p = fmaf(p, r, 4.1666666667e-2f);
    p = fmaf(p, r, 1.6666666667e-1f);
    p = fmaf(p, r, 0.5f);
    float y = fmaf(p, r * r, r) + 1.0f;
    int ki = (int)k;
    float s = __int_as_float((ki + 127) << 23);
    return y * s;
}
__device__ __forceinline__ float sigmoid_acc(float x) {
    return __frcp_rn(1.0f + exp_acc(-x));
}
__device__ __forceinline__ float tanh_acc(float x) {
    float ax = fabsf(x);
    float e = exp_acc(2.0f * ax);
    float t = fmaf(-2.0f, __frcp_rn(e + 1.0f), 1.0f);
    return (x < 0.f) ? -t : t;
}

// ---------------- precompute: W_comb = W_ih @ W_enc (Kahan) -----------------
__global__ void __launch_bounds__(256) precompute_wcomb(
    const float* __restrict__ W_ih, const float* __restrict__ W_enc)
{
    __shared__ float wih[8][H];
    int r0 = blockIdx.x * 8;
    for (int i = threadIdx.x; i < 8 * H; i += 256)
        wih[i >> 10][i & (H - 1)] = W_ih[(size_t)r0 * H + i];
    __syncthreads();
    int d0 = threadIdx.x, d1 = threadIdx.x + 256;
    float s[16], c[16];
    #pragma unroll
    for (int j = 0; j < 16; j++) { s[j] = 0.f; c[j] = 0.f; }
    for (int k = 0; k < H; k++) {
        float e0 = __ldg(&W_enc[(size_t)k * D + d0]);
        float e1 = __ldg(&W_enc[(size_t)k * D + d1]);
        #pragma unroll
        for (int j = 0; j < 8; j++) {
            float w = wih[j][k];
            float tp = __fmul_rn(w, e0);
            float y  = __fsub_rn(tp, c[2*j]);
            float s2 = __fadd_rn(s[2*j], y);
            c[2*j]   = __fsub_rn(__fsub_rn(s2, s[2*j]), y);
            s[2*j]   = s2;
            tp = __fmul_rn(w, e1);
            y  = __fsub_rn(tp, c[2*j+1]);
            s2 = __fadd_rn(s[2*j+1], y);
            c[2*j+1] = __fsub_rn(__fsub_rn(s2, s[2*j+1]), y);
            s[2*j+1] = s2;
        }
    }
    #pragma unroll
    for (int j = 0; j < 8; j++) {
        g_Wcomb[(size_t)(r0 + j) * D + d0] = s[2*j];
        g_Wcomb[(size_t)(r0 + j) * D + d1] = s[2*j+1];
    }
}

__global__ void precompute_bcomb(
    const float* __restrict__ W_ih, const float* __restrict__ b_enc,
    const float* __restrict__ b_gru)
{
    int r = blockIdx.x * blockDim.x + threadIdx.x;
    if (r < H3) {
        const float* wi = W_ih + (size_t)r * H;
        double acc = (double)b_gru[r];
        for (int k = 0; k < H; k++)
            acc += (double)wi[k] * (double)b_enc[k];
        g_bcomb[r] = (float)acc;
    }
}

// ---------------- pack phase-A weights (transposed + interleaved) ----------
__global__ void __launch_bounds__(256) pack_A(const float* __restrict__ W_hh)
{
    int idx = blockIdx.x * 256 + threadIdx.x;   // j*KPA + kp
    int j  = idx / KPA;
    int kp = idx - j * KPA;
    int blk = j >> 3, c = j & 7, cg = c >> 1, ci = c & 1;
    float v[3][2];
    #pragma unroll
    for (int g = 0; g < 3; g++) {
        #pragma unroll
        for (int e = 0; e < 2; e++) {
            int f = 2 * kp + e;
            v[g][e] = (f < D)
                ? g_Wcomb[(size_t)(g * H + j) * D + f]
                : W_hh[(size_t)(g * H + j) * H + (f - D)];
        }
    }
    g_WArz[(blk * KPA + kp) * 8 + c] =
        make_ulonglong2(packf2(v[0][0], v[0][1]), packf2(v[1][0], v[1][1]));
    ((ull*)&g_WAn[(blk * KPA + kp) * 4 + cg])[ci] = packf2(v[2][0], v[2][1]);
}

// ---------------- pack decoder weights -------------------------------------
__global__ void __launch_bounds__(256) pack_D(const float* __restrict__ W_dec)
{
    int idx = blockIdx.x * 256 + threadIdx.x;   // d*KPH + kp
    int d  = idx / KPH;
    int kp = idx - d * KPH;
    int blk = d >> 2, dof = d & 3;
    float m0 = W_dec[(size_t)d * H + 2 * kp];
    float m1 = W_dec[(size_t)d * H + 2 * kp + 1];
    float s0 = W_dec[(size_t)(D + d) * H + 2 * kp];
    float s1 = W_dec[(size_t)(D + d) * H + 2 * kp + 1];
    g_WD[(blk * KPH + kp) * 4 + dof] =
        make_ulonglong2(packf2(m0, m1), packf2(s0, s1));
}

// ---------------- init: x0 into act[0].x, zero act[0].h --------------------
__global__ void init_state(const float* __restrict__ x0)  // [B, D]
{
    int i = blockIdx.x * blockDim.x + threadIdx.x;
    if (i < B * D) {
        int b = i >> 9, d = i & (D - 1);
        ((float*)g_act[0])[(((d >> 1) * B) + b) * 2 + (d & 1)] = x0[i];
    }
    if (i < KPH * B) g_act[0][KPX * B + i] = 0ull;
}

// ---------------- grid-wide barrier -----------------------------------------
__device__ __forceinline__ void grid_sync() {
    __syncthreads();
    if (threadIdx.x == 0) {
        unsigned ticket;
        asm volatile("atom.add.release.gpu.global.u32 %0, [%1], 1;"
                     : "=r"(ticket) : "l"(&g_arrive) : "memory");
        unsigned n = gridDim.x;
        unsigned target = ticket - (ticket % n) + n;
        unsigned v;
        do {
            asm volatile("ld.acquire.gpu.global.u32 %0, [%1];"
                         : "=r"(v) : "l"(&g_arrive) : "memory");
        } while (v < target);
    }
    __syncthreads();
}

// ---------------- persistent GRU kernel -------------------------------------
// 128 blocks x 256 threads (one wave; co-residency guaranteed).
// Phase A: block owns 8 gate columns (j = blk*8+c); warps split K (32 x-kps +
//          64 h-kps each); lane = colgroup(4) x batchquad(8); acc in f32x2.
// Phase B: block owns 4 decode dims (d = blk*4+dof); warps split K (64 kps);
//          weight ulonglong2 packs (mu,logstd) rows so sampling needs no swap.
__global__ void __launch_bounds__(NTHR, 1) gru_persistent(
    const float* __restrict__ b_n,
    const float* __restrict__ b_dec,
    const float* __restrict__ eps,
    float* __restrict__ out,
    int steps)
{
    extern __shared__ ull smP[];    // 8 warps * 32 lanes * 32 ull = 64 KB
    const int tid  = threadIdx.x;
    const int lane = tid & 31;
    const int w    = tid >> 5;
    const int blk  = blockIdx.x;

    const int cg = lane >> 3;       // col group (cols 2cg, 2cg+1)
    const int bq = lane & 7;        // batch quad (batches 4bq..4bq+3)

    const size_t plane = (size_t)steps * (B * D);

    const ulonglong2* wrzB = g_WArz + (size_t)blk * KPA * 8 + 2 * cg;
    const ulonglong2* wnB  = g_WAn  + (size_t)blk * KPA * 4 + cg;
    const ulonglong2* wdB  = g_WD   + (size_t)blk * KPH * 4 + (lane >> 3);

    for (int t = 0; t < steps; t++) {
        const ull* actR = g_act[t & 1];
        ull*       actW = g_act[(t & 1) ^ 1];

        // ================= phase A: gate GEMMs (K-split) =================
        ull aR[2][4], aZ[2][4], aNx[2][4], aNh[2][4];
        #pragma unroll
        for (int ci = 0; ci < 2; ci++)
            #pragma unroll
            for (int bi = 0; bi < 4; bi++)
                { aR[ci][bi]=0; aZ[ci][bi]=0; aNx[ci][bi]=0; aNh[ci][bi]=0; }

#define PHA_BODY(KP, AN)                                                      \
        {                                                                     \
            int kp = (KP);                                                    \
            ulonglong2 a01 = ldcg2(actR + kp * B + bq * 4);                   \
            ulonglong2 a23 = ldcg2(actR + kp * B + bq * 4 + 2);               \
            ulonglong2 rz0 = ldg2(wrzB + kp * 8);                             \
            ulonglong2 rz1 = ldg2(wrzB + kp * 8 + 1);                         \
            ulonglong2 nn  = ldg2(wnB  + kp * 4);                             \
            ull av[4] = { a01.x, a01.y, a23.x, a23.y };                       \
            _Pragma("unroll")                                                 \
            for (int bi = 0; bi < 4; bi++) {                                  \
                fma2(aR[0][bi], rz0.x, av[bi]);                               \
                fma2(aZ[0][bi], rz0.y, av[bi]);                               \
                fma2(AN[0][bi], nn.x,  av[bi]);                               \
                fma2(aR[1][bi], rz1.x, av[bi]);                               \
                fma2(aZ[1][bi], rz1.y, av[bi]);                               \
                fma2(AN[1][bi], nn.y,  av[bi]);                               \
            }                                                                 \
        }

        {   // x part: 32 kps per warp
            int kp0 = w * 32;
            #pragma unroll 2
            for (int q = 0; q < 32; q++) PHA_BODY(kp0 + q, aNx)
        }
        {   // h part: 64 kps per warp
            int kp0 = KPX + w * 64;
            #pragma unroll 2
            for (int q = 0; q < 64; q++) PHA_BODY(kp0 + q, aNh)
        }
#undef PHA_BODY

        {   // store partials: idx = g*8 + ci*4 + bi
            ull* p = smP + (size_t)(w * 32 + lane) * 32;
            #pragma unroll
            for (int ci = 0; ci < 2; ci++)
                #pragma unroll
                for (int bi = 0; bi < 4; bi++) {
                    p[ 0 + ci*4 + bi] = aR [ci][bi];
                    p[ 8 + ci*4 + bi] = aZ [ci][bi];
                    p[16 + ci*4 + bi] = aNx[ci][bi];
                    p[24 + ci*4 + bi] = aNh[ci][bi];
                }
        }
        __syncthreads();

        {   // gating: thread (cG, b) -> h_new[j][b]
            int cG = tid >> 5, b = tid & 31;
            int cgg = cG >> 1, cii = cG & 1, bqq = b >> 2, bii = b & 3;
            int off = cii * 4 + bii;
            ull sR = 0, sZ = 0, sNx = 0, sNh = 0;
            #pragma unroll
            for (int ww = 0; ww < 8; ww++) {
                const ull* p = smP + (size_t)(ww * 32 + cgg * 8 + bqq) * 32;
                add2(sR,  p[ 0 + off]);
                add2(sZ,  p[ 8 + off]);
                add2(sNx, p[16 + off]);
                add2(sNh, p[24 + off]);
            }
            int j = blk * 8 + cG;
            float2 u;
            u = upk(sR);  float pr  = u.x + u.y + g_bcomb[j];
            u = upk(sZ);  float pz  = u.x + u.y + g_bcomb[H + j];
            u = upk(sNx); float inx = u.x + u.y + g_bcomb[2 * H + j];
            u = upk(sNh); float hnv = u.x + u.y;
            float r = sigmoid_acc(pr);
            float z = sigmoid_acc(pz);
            float n = tanh_acc(fmaf(r, hnv + __ldg(b_n + j), inx));
            int fi = ((KPX + (j >> 1)) * B + b) * 2 + (j & 1);
            float hp = ldcg_f((const float*)actR + fi);
            ((float*)actW)[fi] = n + z * (hp - n);
        }
        grid_sync();

        // ================= phase B: decoder + sampling =================
        ull AM[4], AS[4];
        #pragma unroll
        for (int bi = 0; bi < 4; bi++) { AM[bi] = 0; AS[bi] = 0; }
        {
            int kp0 = w * 64;
            #pragma unroll 2
            for (int q = 0; q < 64; q++) {
                int kp = kp0 + q;
                ulonglong2 a01 = ldcg2(actW + (KPX + kp) * B + bq * 4);
                ulonglong2 a23 = ldcg2(actW + (KPX + kp) * B + bq * 4 + 2);
                ulonglong2 wv  = ldg2(wdB + kp * 4);
                ull av[4] = { a01.x, a01.y, a23.x, a23.y };
                #pragma unroll
                for (int bi = 0; bi < 4; bi++) {
                    fma2(AM[bi], wv.x, av[bi]);
                    fma2(AS[bi], wv.y, av[bi]);
                }
            }
        }
        __syncthreads();   // smP reuse is safe: phase-A readers passed grid_sync
        {
            ull* p = smP + (size_t)(w * 32 + lane) * 8;
            #pragma unroll
            for (int bi = 0; bi < 4; bi++) {
                p[bi]     = AM[bi];
                p[4 + bi] = AS[bi];
            }
        }
        __syncthreads();
        if (tid < 128) {
            int dof = tid >> 5, b = tid & 31, bqq = b >> 2, bii = b & 3;
            ull sM = 0, sS = 0;
            #pragma unroll
            for (int ww = 0; ww < 8; ww++) {
                const ull* p = smP + (size_t)(ww * 32 + dof * 8 + bqq) * 8;
                add2(sM, p[bii]);
                add2(sS, p[4 + bii]);
            }
            int d = blk * 4 + dof;
            float2 u;
            u = upk(sM); float mu = u.x + u.y + __ldg(b_dec + d);
            u = upk(sS); float ls = u.x + u.y + __ldg(b_dec + D + d);
            float sig = exp_acc(ls);
            size_t o = (size_t)t * (B * D) + (size_t)b * D + d;
            float xn = fmaf(sig, __ldg(eps + o), mu);
            ((float*)actW)[(((d >> 1) * B) + b) * 2 + (d & 1)] = xn;
            out[o]             = xn;
            out[plane + o]     = mu;
            out[2 * plane + o] = sig;
        }
        grid_sync();
    }
}

// ---------------- launch ----------------------------------------------------
extern "C" void kernel_launch(void* const* d_in, const int* in_sizes, int n_in,
                              void* d_out, int out_size)
{
    const float* x0    = (const float*)d_in[0];
    const float* eps   = (const float*)d_in[1];
    const float* W_enc = (const float*)d_in[2];
    const float* b_enc = (const float*)d_in[3];
    const float* W_ih  = (const float*)d_in[4];
    const float* W_hh  = (const float*)d_in[5];
    const float* b_gru = (const float*)d_in[6];
    const float* b_n   = (const float*)d_in[7];
    const float* W_dec = (const float*)d_in[8];
    const float* b_dec = (const float*)d_in[9];

    int steps = in_sizes[1] / (B * D);
    float* out = (float*)d_out;

    const int smem_bytes = 8 * 32 * 32 * sizeof(ull);   // 64 KB
    cudaFuncSetAttribute(gru_persistent,
                         cudaFuncAttributeMaxDynamicSharedMemorySize, smem_bytes);

    precompute_wcomb<<<H3 / 8, 256>>>(W_ih, W_enc);
    precompute_bcomb<<<(H3 + 255) / 256, 256>>>(W_ih, b_enc, b_gru);
    pack_A<<<(H * KPA) / 256, 256>>>(W_hh);
    pack_D<<<(D * KPH) / 256, 256>>>(W_dec);
    init_state<<<(KPH * B + 255) / 256, 256>>>(x0);
    gru_persistent<<<NBLK, NTHR, smem_bytes>>>(b_n, b_dec, eps, out, steps);
}

// round 5
// speedup vs baseline: 1.5662x; 1.3635x over previous
#include <cuda_runtime.h>
#include <math.h>

#define B 32
#define D 512
#define H 1024
#define H3 (3*H)
#define NBLK 128
#define NTHR 256
#define KPX 256            // x feature-pairs
#define KPH 512            // h feature-pairs
#define KPA (KPX+KPH)      // 768 combined feature-pairs (phase A)
#define SSTRIDE 33         // padded smem slot stride (ull) — conflict-free

typedef unsigned long long ull;

// ---------------- persistent device scratch --------------------------------
__device__ __align__(16) float g_Wcomb[H3 * D];            // temp: W_ih @ W_enc
__device__ float g_bcomb[H3];
// phase A weights, packed: per (blk, kp, col c): ulonglong2{ r-pair, z-pair }
__device__ __align__(16) ulonglong2 g_WArz[NBLK * KPA * 8];
// n-gate pairs: per (blk, kp, colgroup cg): ulonglong2{ n-pair col 2cg, col 2cg+1 }
__device__ __align__(16) ulonglong2 g_WAn [NBLK * KPA * 4];
// decoder: per (blk, kp, dof): ulonglong2{ mu-row pair, logstd-row pair }
__device__ __align__(16) ulonglong2 g_WD  [NBLK * KPH * 4];
// activations, f32x2 feature-pairs: [kp][batch]; kp<256 = x, kp>=256 = h
__device__ __align__(16) ull g_act[2][KPA * B];
__device__ unsigned g_arrive;

// ---------------- packed f32x2 helpers --------------------------------------
__device__ __forceinline__ void fma2(ull& acc, ull a, ull b) {
    asm("fma.rn.f32x2 %0, %1, %2, %0;" : "+l"(acc) : "l"(a), "l"(b));
}
__device__ __forceinline__ void add2(ull& acc, ull a) {
    asm("add.rn.f32x2 %0, %0, %1;" : "+l"(acc) : "l"(a));
}
__device__ __forceinline__ float2 upk(ull u) {
    float a, b;
    asm("mov.b64 {%0, %1}, %2;" : "=f"(a), "=f"(b) : "l"(u));
    return make_float2(a, b);
}
__device__ __forceinline__ ull packf2(float lo, float hi) {
    ull u; asm("mov.b64 %0, {%1, %2};" : "=l"(u) : "f"(lo), "f"(hi)); return u;
}

// ---------------- fast-math-immune precise fp32 transcendentals ------------
__device__ __forceinline__ float exp_acc(float x) {
    x = fminf(fmaxf(x, -80.f), 80.f);
    float t = fmaf(x, 1.4426950408889634f, 12582912.f);
    float k = t - 12582912.f;
    float r = fmaf(k, -0.693359375f, x);
    r = fmaf(k, 2.12194440054690583e-4f, r);
    float p = 1.9841269841e-4f;
    p = fmaf(p, r, 1.3888888889e-3f);
    p = fmaf(p, r, 8.3333333333e-3f);
    p = fmaf(p, r, 4.1666666667e-2f);
    p = fmaf(p, r, 1.6666666667e-1f);
    p = fmaf(p, r, 0.5f);
    float y = fmaf(p, r * r, r) + 1.0f;
    int ki = (int)k;
    float s = __int_as_float((ki + 127) << 23);
    return y * s;
}
__device__ __forceinline__ float sigmoid_acc(float x) {
    return __frcp_rn(1.0f + exp_acc(-x));
}
__device__ __forceinline__ float tanh_acc(float x) {
    float ax = fabsf(x);
    float e = exp_acc(2.0f * ax);
    float t = fmaf(-2.0f, __frcp_rn(e + 1.0f), 1.0f);
    return (x < 0.f) ? -t : t;
}

// ---------------- precompute: W_comb = W_ih @ W_enc (Kahan) -----------------
__global__ void __launch_bounds__(256) precompute_wcomb(
    const float* __restrict__ W_ih, const float* __restrict__ W_enc)
{
    __shared__ float wih[8][H];
    int r0 = blockIdx.x * 8;
    for (int i = threadIdx.x; i < 8 * H; i += 256)
        wih[i >> 10][i & (H - 1)] = W_ih[(size_t)r0 * H + i];
    __syncthreads();
    int d0 = threadIdx.x, d1 = threadIdx.x + 256;
    float s[16], c[16];
    #pragma unroll
    for (int j = 0; j < 16; j++) { s[j] = 0.f; c[j] = 0.f; }
    for (int k = 0; k < H; k++) {
        float e0 = __ldg(&W_enc[(size_t)k * D + d0]);
        float e1 = __ldg(&W_enc[(size_t)k * D + d1]);
        #pragma unroll
        for (int j = 0; j < 8; j++) {
            float w = wih[j][k];
            float tp = __fmul_rn(w, e0);
            float y  = __fsub_rn(tp, c[2*j]);
            float s2 = __fadd_rn(s[2*j], y);
            c[2*j]   = __fsub_rn(__fsub_rn(s2, s[2*j]), y);
            s[2*j]   = s2;
            tp = __fmul_rn(w, e1);
            y  = __fsub_rn(tp, c[2*j+1]);
            s2 = __fadd_rn(s[2*j+1], y);
            c[2*j+1] = __fsub_rn(__fsub_rn(s2, s[2*j+1]), y);
            s[2*j+1] = s2;
        }
    }
    #pragma unroll
    for (int j = 0; j < 8; j++) {
        g_Wcomb[(size_t)(r0 + j) * D + d0] = s[2*j];
        g_Wcomb[(size_t)(r0 + j) * D + d1] = s[2*j+1];
    }
}

// ---------------- fused pack: pack_A + pack_D + bcomb ----------------------
#define NPA ((H * KPA) / 256)     // 3072 blocks for pack_A
#define NPD ((D * KPH) / 256)     // 1024 blocks for pack_D
#define NPB ((H3 + 255) / 256)    // 12 blocks for bcomb

__global__ void __launch_bounds__(256) fused_pack(
    const float* __restrict__ W_hh,
    const float* __restrict__ W_dec,
    const float* __restrict__ W_ih,
    const float* __restrict__ b_enc,
    const float* __restrict__ b_gru)
{
    int bid = blockIdx.x;
    if (bid < NPA) {
        int idx = bid * 256 + threadIdx.x;   // j*KPA + kp
        int j  = idx / KPA;
        int kp = idx - j * KPA;
        int blk = j >> 3, c = j & 7, cg = c >> 1, ci = c & 1;
        float v[3][2];
        #pragma unroll
        for (int g = 0; g < 3; g++)
            #pragma unroll
            for (int e = 0; e < 2; e++) {
                int f = 2 * kp + e;
                v[g][e] = (f < D)
                    ? g_Wcomb[(size_t)(g * H + j) * D + f]
                    : W_hh[(size_t)(g * H + j) * H + (f - D)];
            }
        g_WArz[(blk * KPA + kp) * 8 + c] =
            make_ulonglong2(packf2(v[0][0], v[0][1]), packf2(v[1][0], v[1][1]));
        ((ull*)&g_WAn[(blk * KPA + kp) * 4 + cg])[ci] = packf2(v[2][0], v[2][1]);
    } else if (bid < NPA + NPD) {
        int idx = (bid - NPA) * 256 + threadIdx.x;   // d*KPH + kp
        int d  = idx / KPH;
        int kp = idx - d * KPH;
        int blk = d >> 2, dof = d & 3;
        float m0 = W_dec[(size_t)d * H + 2 * kp];
        float m1 = W_dec[(size_t)d * H + 2 * kp + 1];
        float s0 = W_dec[(size_t)(D + d) * H + 2 * kp];
        float s1 = W_dec[(size_t)(D + d) * H + 2 * kp + 1];
        g_WD[(blk * KPH + kp) * 4 + dof] =
            make_ulonglong2(packf2(m0, m1), packf2(s0, s1));
    } else {
        int r = (bid - NPA - NPD) * 256 + threadIdx.x;
        if (r < H3) {
            const float* wi = W_ih + (size_t)r * H;
            double acc = (double)b_gru[r];
            for (int k = 0; k < H; k++)
                acc += (double)wi[k] * (double)b_enc[k];
            g_bcomb[r] = (float)acc;
        }
    }
}

// ---------------- init: x0 into act[0].x, zero act[0].h --------------------
__global__ void init_state(const float* __restrict__ x0)  // [B, D]
{
    int i = blockIdx.x * blockDim.x + threadIdx.x;
    if (i < B * D) {
        int b = i >> 9, d = i & (D - 1);
        ((float*)g_act[0])[(((d >> 1) * B) + b) * 2 + (d & 1)] = x0[i];
    }
    if (i < KPH * B) g_act[0][KPX * B + i] = 0ull;
}

// ---------------- grid-wide barrier -----------------------------------------
__device__ __forceinline__ void grid_sync() {
    __syncthreads();
    if (threadIdx.x == 0) {
        unsigned ticket;
        asm volatile("atom.add.release.gpu.global.u32 %0, [%1], 1;"
                     : "=r"(ticket) : "l"(&g_arrive) : "memory");
        unsigned n = gridDim.x;
        unsigned target = ticket - (ticket % n) + n;
        unsigned v;
        do {
            asm volatile("ld.acquire.gpu.global.u32 %0, [%1];"
                         : "=r"(v) : "l"(&g_arrive) : "memory");
        } while (v < target);
    }
    __syncthreads();
}

// ---------------- persistent GRU kernel -------------------------------------
// 128 blocks x 256 threads. Phase A: block owns 8 gate columns; warps split K
// (32 x-kps + 64 h-kps each); lane = colgroup(4) x batchquad(8); f32x2 accs.
// Partials reduced through padded, conflict-free smem. Phase B: block owns 4
// decode dims; warps split K (64 kps each).
__global__ void __launch_bounds__(NTHR, 1) gru_persistent(
    const float* __restrict__ b_n,
    const float* __restrict__ b_dec,
    const float* __restrict__ eps,
    float* __restrict__ out,
    int steps)
{
    extern __shared__ ull smP[];    // 256 slots * 33 ull = 67.6 KB
    const int tid  = threadIdx.x;
    const int lane = tid & 31;
    const int w    = tid >> 5;
    const int blk  = blockIdx.x;

    const int cg = lane >> 3;       // col group (cols 2cg, 2cg+1)
    const int bq = lane & 7;        // batch quad (batches 4bq..4bq+3)

    const size_t plane = (size_t)steps * (B * D);

    const ulonglong2* wrzB = g_WArz + (size_t)blk * KPA * 8 + 2 * cg;
    const ulonglong2* wnB  = g_WAn  + (size_t)blk * KPA * 4 + cg;
    const ulonglong2* wdB  = g_WD   + (size_t)blk * KPH * 4 + cg;

    for (int t = 0; t < steps; t++) {
        const ull* actR = g_act[t & 1];
        ull*       actW = g_act[(t & 1) ^ 1];

        // ================= phase A: gate GEMMs (K-split) =================
        ull aR[2][4], aZ[2][4], aNx[2][4], aNh[2][4];
        #pragma unroll
        for (int ci = 0; ci < 2; ci++)
            #pragma unroll
            for (int bi = 0; bi < 4; bi++)
                { aR[ci][bi]=0; aZ[ci][bi]=0; aNx[ci][bi]=0; aNh[ci][bi]=0; }

#define PHA_BODY(KP, AN)                                                      \
        {                                                                     \
            int kp = (KP);                                                    \
            ulonglong2 a01 = __ldcg((const ulonglong2*)(actR + kp * B + bq * 4));     \
            ulonglong2 a23 = __ldcg((const ulonglong2*)(actR + kp * B + bq * 4 + 2)); \
            ulonglong2 rz0 = __ldg(wrzB + kp * 8);                            \
            ulonglong2 rz1 = __ldg(wrzB + kp * 8 + 1);                        \
            ulonglong2 nn  = __ldg(wnB  + kp * 4);                            \
            ull av[4] = { a01.x, a01.y, a23.x, a23.y };                       \
            _Pragma("unroll")                                                 \
            for (int bi = 0; bi < 4; bi++) {                                  \
                fma2(aR[0][bi], rz0.x, av[bi]);                               \
                fma2(aZ[0][bi], rz0.y, av[bi]);                               \
                fma2(AN[0][bi], nn.x,  av[bi]);                               \
                fma2(aR[1][bi], rz1.x, av[bi]);                               \
                fma2(aZ[1][bi], rz1.y, av[bi]);                               \
                fma2(AN[1][bi], nn.y,  av[bi]);                               \
            }                                                                 \
        }

        {   // x part: 32 kps per warp
            int kp0 = w * 32;
            #pragma unroll 4
            for (int q = 0; q < 32; q++) PHA_BODY(kp0 + q, aNx)
        }
        {   // h part: 64 kps per warp
            int kp0 = KPX + w * 64;
            #pragma unroll 4
            for (int q = 0; q < 64; q++) PHA_BODY(kp0 + q, aNh)
        }
#undef PHA_BODY

        {   // store partials: idx = ci*16 + bi*4 + g  (conflict-free layout)
            ull* p = smP + (size_t)(w * 32 + lane) * SSTRIDE;
            #pragma unroll
            for (int ci = 0; ci < 2; ci++)
                #pragma unroll
                for (int bi = 0; bi < 4; bi++) {
                    p[ci*16 + bi*4 + 0] = aR [ci][bi];
                    p[ci*16 + bi*4 + 1] = aZ [ci][bi];
                    p[ci*16 + bi*4 + 2] = aNx[ci][bi];
                    p[ci*16 + bi*4 + 3] = aNh[ci][bi];
                }
        }
        __syncthreads();

        {   // gating: thread (cG, b) -> h_new[j][b]
            int cG = tid >> 5, b = tid & 31;
            int cgg = cG >> 1, cii = cG & 1, bqq = b >> 2, bii = b & 3;
            int off = cii * 16 + bii * 4;
            ull sR = 0, sZ = 0, sNx = 0, sNh = 0;
            #pragma unroll
            for (int ww = 0; ww < 8; ww++) {
                const ull* p = smP + (size_t)(ww * 32 + cgg * 8 + bqq) * SSTRIDE;
                add2(sR,  p[off + 0]);
                add2(sZ,  p[off + 1]);
                add2(sNx, p[off + 2]);
                add2(sNh, p[off + 3]);
            }
            int j = blk * 8 + cG;
            float2 u;
            u = upk(sR);  float pr  = u.x + u.y + g_bcomb[j];
            u = upk(sZ);  float pz  = u.x + u.y + g_bcomb[H + j];
            u = upk(sNx); float inx = u.x + u.y + g_bcomb[2 * H + j];
            u = upk(sNh); float hnv = u.x + u.y;
            float r = sigmoid_acc(pr);
            float z = sigmoid_acc(pz);
            float n = tanh_acc(fmaf(r, hnv + __ldg(b_n + j), inx));
            int fi = ((KPX + (j >> 1)) * B + b) * 2 + (j & 1);
            float hp = __ldcg((const float*)actR + fi);
            ((float*)actW)[fi] = n + z * (hp - n);
        }
        grid_sync();

        // ================= phase B: decoder + sampling =================
        ull AM[4], AS[4];
        #pragma unroll
        for (int bi = 0; bi < 4; bi++) { AM[bi] = 0; AS[bi] = 0; }
        {
            int kp0 = w * 64;
            #pragma unroll 4
            for (int q = 0; q < 64; q++) {
                int kp = kp0 + q;
                ulonglong2 a01 = __ldcg((const ulonglong2*)(actW + (KPX + kp) * B + bq * 4));
                ulonglong2 a23 = __ldcg((const ulonglong2*)(actW + (KPX + kp) * B + bq * 4 + 2));
                ulonglong2 wv  = __ldg(wdB + kp * 4);
                ull av[4] = { a01.x, a01.y, a23.x, a23.y };
                #pragma unroll
                for (int bi = 0; bi < 4; bi++) {
                    fma2(AM[bi], wv.x, av[bi]);
                    fma2(AS[bi], wv.y, av[bi]);
                }
            }
        }
        __syncthreads();   // smP reuse safe: phase-A readers passed grid_sync
        {   // store partials: idx = m*16 + bi*4 (conflict-free)
            ull* p = smP + (size_t)(w * 32 + lane) * SSTRIDE;
            #pragma unroll
            for (int bi = 0; bi < 4; bi++) {
                p[bi*4]      = AM[bi];
                p[16 + bi*4] = AS[bi];
            }
        }
        __syncthreads();
        if (tid < 128) {
            int dof = tid >> 5, b = tid & 31, bqq = b >> 2, bii = b & 3;
            ull sM = 0, sS = 0;
            #pragma unroll
            for (int ww = 0; ww < 8; ww++) {
                const ull* p = smP + (size_t)(ww * 32 + dof * 8 + bqq) * SSTRIDE;
                add2(sM, p[bii*4]);
                add2(sS, p[16 + bii*4]);
            }
            int d = blk * 4 + dof;
            float2 u;
            u = upk(sM); float mu = u.x + u.y + __ldg(b_dec + d);
            u = upk(sS); float ls = u.x + u.y + __ldg(b_dec + D + d);
            float sig = exp_acc(ls);
            size_t o = (size_t)t * (B * D) + (size_t)b * D + d;
            float xn = fmaf(sig, __ldg(eps + o), mu);
            ((float*)actW)[(((d >> 1) * B) + b) * 2 + (d & 1)] = xn;
            out[o]             = xn;
            out[plane + o]     = mu;
            out[2 * plane + o] = sig;
        }
        grid_sync();
    }
}

// ---------------- launch ----------------------------------------------------
extern "C" void kernel_launch(void* const* d_in, const int* in_sizes, int n_in,
                              void* d_out, int out_size)
{
    const float* x0    = (const float*)d_in[0];
    const float* eps   = (const float*)d_in[1];
    const float* W_enc = (const float*)d_in[2];
    const float* b_enc = (const float*)d_in[3];
    const float* W_ih  = (const float*)d_in[4];
    const float* W_hh  = (const float*)d_in[5];
    const float* b_gru = (const float*)d_in[6];
    const float* b_n   = (const float*)d_in[7];
    const float* W_dec = (const float*)d_in[8];
    const float* b_dec = (const float*)d_in[9];

    int steps = in_sizes[1] / (B * D);
    float* out = (float*)d_out;

    const int smem_bytes = NTHR * SSTRIDE * sizeof(ull);   // 67584
    cudaFuncSetAttribute(gru_persistent,
                         cudaFuncAttributeMaxDynamicSharedMemorySize, smem_bytes);

    precompute_wcomb<<<H3 / 8, 256>>>(W_ih, W_enc);
    fused_pack<<<NPA + NPD + NPB, 256>>>(W_hh, W_dec, W_ih, b_enc, b_gru);
    init_state<<<(KPH * B + 255) / 256, 256>>>(x0);
    gru_persistent<<<NBLK, NTHR, smem_bytes>>>(b_n, b_dec, eps, out, steps);
}

// round 6
// speedup vs baseline: 1.6872x; 1.0773x over previous
#include <cuda_runtime.h>
#include <math.h>

#define B 32
#define D 512
#define H 1024
#define H3 (3*H)
#define NBLK 128
#define NTHR 512
#define NW   16            // warps per block
#define KPX 256            // x feature-pairs
#define KPH 512            // h feature-pairs
#define KPA (KPX+KPH)      // 768 combined feature-pairs (phase A)
#define SSTRIDE 33         // padded smem slot stride (ull) — conflict-free

typedef unsigned long long ull;

// ---------------- persistent device scratch --------------------------------
__device__ __align__(16) float g_Wcomb[H3 * D];            // temp: W_ih @ W_enc
__device__ float g_bcomb[H3];
// phase A weights, packed: per (blk, kp, col c): ulonglong2{ r-pair, z-pair }
__device__ __align__(16) ulonglong2 g_WArz[NBLK * KPA * 8];
// n-gate pairs: per (blk, kp, colgroup cg): ulonglong2{ n-pair col 2cg, col 2cg+1 }
__device__ __align__(16) ulonglong2 g_WAn [NBLK * KPA * 4];
// decoder: per (blk, kp, dof): ulonglong2{ mu-row pair, logstd-row pair }
__device__ __align__(16) ulonglong2 g_WD  [NBLK * KPH * 4];
// activations, f32x2 feature-pairs: [kp][batch]; kp<256 = x, kp>=256 = h
__device__ __align__(16) ull g_act[2][KPA * B];
__device__ unsigned g_arrive;

// ---------------- packed f32x2 helpers --------------------------------------
__device__ __forceinline__ void fma2(ull& acc, ull a, ull b) {
    asm("fma.rn.f32x2 %0, %1, %2, %0;" : "+l"(acc) : "l"(a), "l"(b));
}
__device__ __forceinline__ void add2(ull& acc, ull a) {
    asm("add.rn.f32x2 %0, %0, %1;" : "+l"(acc) : "l"(a));
}
__device__ __forceinline__ float2 upk(ull u) {
    float a, b;
    asm("mov.b64 {%0, %1}, %2;" : "=f"(a), "=f"(b) : "l"(u));
    return make_float2(a, b);
}
__device__ __forceinline__ ull packf2(float lo, float hi) {
    ull u; asm("mov.b64 %0, {%1, %2};" : "=l"(u) : "f"(lo), "f"(hi)); return u;
}

// ---------------- fast-math-immune precise fp32 transcendentals ------------
__device__ __forceinline__ float exp_acc(float x) {
    x = fminf(fmaxf(x, -80.f), 80.f);
    float t = fmaf(x, 1.4426950408889634f, 12582912.f);
    float k = t - 12582912.f;
    float r = fmaf(k, -0.693359375f, x);
    r = fmaf(k, 2.12194440054690583e-4f, r);
    float p = 1.9841269841e-4f;
    p = fmaf(p, r, 1.3888888889e-3f);
    p = fmaf(p, r, 8.3333333333e-3f);
    p = fmaf(p, r, 4.1666666667e-2f);
    p = fmaf(p, r, 1.6666666667e-1f);
    p = fmaf(p, r, 0.5f);
    float y = fmaf(p, r * r, r) + 1.0f;
    int ki = (int)k;
    float s = __int_as_float((ki + 127) << 23);
    return y * s;
}
__device__ __forceinline__ float sigmoid_acc(float x) {
    return __frcp_rn(1.0f + exp_acc(-x));
}
__device__ __forceinline__ float tanh_acc(float x) {
    float ax = fabsf(x);
    float e = exp_acc(2.0f * ax);
    float t = fmaf(-2.0f, __frcp_rn(e + 1.0f), 1.0f);
    return (x < 0.f) ? -t : t;
}

// ---------------- precompute: W_comb = W_ih @ W_enc (Kahan) -----------------
__global__ void __launch_bounds__(256) precompute_wcomb(
    const float* __restrict__ W_ih, const float* __restrict__ W_enc)
{
    __shared__ float wih[8][H];
    int r0 = blockIdx.x * 8;
    for (int i = threadIdx.x; i < 8 * H; i += 256)
        wih[i >> 10][i & (H - 1)] = W_ih[(size_t)r0 * H + i];
    __syncthreads();
    int d0 = threadIdx.x, d1 = threadIdx.x + 256;
    float s[16], c[16];
    #pragma unroll
    for (int j = 0; j < 16; j++) { s[j] = 0.f; c[j] = 0.f; }
    for (int k = 0; k < H; k++) {
        float e0 = __ldg(&W_enc[(size_t)k * D + d0]);
        float e1 = __ldg(&W_enc[(size_t)k * D + d1]);
        #pragma unroll
        for (int j = 0; j < 8; j++) {
            float w = wih[j][k];
            float tp = __fmul_rn(w, e0);
            float y  = __fsub_rn(tp, c[2*j]);
            float s2 = __fadd_rn(s[2*j], y);
            c[2*j]   = __fsub_rn(__fsub_rn(s2, s[2*j]), y);
            s[2*j]   = s2;
            tp = __fmul_rn(w, e1);
            y  = __fsub_rn(tp, c[2*j+1]);
            s2 = __fadd_rn(s[2*j+1], y);
            c[2*j+1] = __fsub_rn(__fsub_rn(s2, s[2*j+1]), y);
            s[2*j+1] = s2;
        }
    }
    #pragma unroll
    for (int j = 0; j < 8; j++) {
        g_Wcomb[(size_t)(r0 + j) * D + d0] = s[2*j];
        g_Wcomb[(size_t)(r0 + j) * D + d1] = s[2*j+1];
    }
}

// ---------------- fused pack: pack_A + pack_D + bcomb ----------------------
#define NPA ((H * KPA) / 256)     // 3072 blocks for pack_A
#define NPD ((D * KPH) / 256)     // 1024 blocks for pack_D
#define NPB ((H3 + 255) / 256)    // 12 blocks for bcomb

__global__ void __launch_bounds__(256) fused_pack(
    const float* __restrict__ W_hh,
    const float* __restrict__ W_dec,
    const float* __restrict__ W_ih,
    const float* __restrict__ b_enc,
    const float* __restrict__ b_gru)
{
    int bid = blockIdx.x;
    if (bid < NPA) {
        int idx = bid * 256 + threadIdx.x;   // j*KPA + kp
        int j  = idx / KPA;
        int kp = idx - j * KPA;
        int blk = j >> 3, c = j & 7, cg = c >> 1, ci = c & 1;
        float v[3][2];
        #pragma unroll
        for (int g = 0; g < 3; g++)
            #pragma unroll
            for (int e = 0; e < 2; e++) {
                int f = 2 * kp + e;
                v[g][e] = (f < D)
                    ? g_Wcomb[(size_t)(g * H + j) * D + f]
                    : W_hh[(size_t)(g * H + j) * H + (f - D)];
            }
        g_WArz[(blk * KPA + kp) * 8 + c] =
            make_ulonglong2(packf2(v[0][0], v[0][1]), packf2(v[1][0], v[1][1]));
        ((ull*)&g_WAn[(blk * KPA + kp) * 4 + cg])[ci] = packf2(v[2][0], v[2][1]);
    } else if (bid < NPA + NPD) {
        int idx = (bid - NPA) * 256 + threadIdx.x;   // d*KPH + kp
        int d  = idx / KPH;
        int kp = idx - d * KPH;
        int blk = d >> 2, dof = d & 3;
        float m0 = W_dec[(size_t)d * H + 2 * kp];
        float m1 = W_dec[(size_t)d * H + 2 * kp + 1];
        float s0 = W_dec[(size_t)(D + d) * H + 2 * kp];
        float s1 = W_dec[(size_t)(D + d) * H + 2 * kp + 1];
        g_WD[(blk * KPH + kp) * 4 + dof] =
            make_ulonglong2(packf2(m0, m1), packf2(s0, s1));
    } else {
        int r = (bid - NPA - NPD) * 256 + threadIdx.x;
        if (r < H3) {
            const float* wi = W_ih + (size_t)r * H;
            double acc = (double)b_gru[r];
            for (int k = 0; k < H; k++)
                acc += (double)wi[k] * (double)b_enc[k];
            g_bcomb[r] = (float)acc;
        }
    }
}

// ---------------- init: x0 into act[0].x, zero act[0].h --------------------
__global__ void init_state(const float* __restrict__ x0)  // [B, D]
{
    int i = blockIdx.x * blockDim.x + threadIdx.x;
    if (i < B * D) {
        int b = i >> 9, d = i & (D - 1);
        ((float*)g_act[0])[(((d >> 1) * B) + b) * 2 + (d & 1)] = x0[i];
    }
    if (i < KPH * B) g_act[0][KPX * B + i] = 0ull;
}

// ---------------- grid-wide barrier -----------------------------------------
__device__ __forceinline__ void grid_sync() {
    __syncthreads();
    if (threadIdx.x == 0) {
        unsigned ticket;
        asm volatile("atom.add.release.gpu.global.u32 %0, [%1], 1;"
                     : "=r"(ticket) : "l"(&g_arrive) : "memory");
        unsigned n = gridDim.x;
        unsigned target = ticket - (ticket % n) + n;
        unsigned v;
        do {
            asm volatile("ld.acquire.gpu.global.u32 %0, [%1];"
                         : "=r"(v) : "l"(&g_arrive) : "memory");
        } while (v < target);
    }
    __syncthreads();
}

// ---------------- persistent GRU kernel -------------------------------------
// 128 blocks x 512 threads (16 warps, 4/SMSP for latency hiding).
// Phase A: block owns 8 gate columns; warps split K (16 x-kps + 32 h-kps each);
// lane = colgroup(4) x batchquad(8); f32x2 accumulators; padded conflict-free
// smem reduction over 16 warps. Phase B: block owns 4 decode dims; 32 kps/warp.
__global__ void __launch_bounds__(NTHR, 1) gru_persistent(
    const float* __restrict__ b_n,
    const float* __restrict__ b_dec,
    const float* __restrict__ eps,
    float* __restrict__ out,
    int steps)
{
    extern __shared__ ull smP[];    // 512 slots * 33 ull = 135 KB
    const int tid  = threadIdx.x;
    const int lane = tid & 31;
    const int w    = tid >> 5;
    const int blk  = blockIdx.x;

    const int cg = lane >> 3;       // col group (cols 2cg, 2cg+1)
    const int bq = lane & 7;        // batch quad (batches 4bq..4bq+3)

    const size_t plane = (size_t)steps * (B * D);

    const ulonglong2* wrzB = g_WArz + (size_t)blk * KPA * 8 + 2 * cg;
    const ulonglong2* wnB  = g_WAn  + (size_t)blk * KPA * 4 + cg;
    const ulonglong2* wdB  = g_WD   + (size_t)blk * KPH * 4 + cg;

    // phase-B output thread constants (tid < 128)
    const int dofO = tid >> 5;
    const int bO   = tid & 31;
    const int dO   = blk * 4 + dofO;

    for (int t = 0; t < steps; t++) {
        const ull* actR = g_act[t & 1];
        ull*       actW = g_act[(t & 1) ^ 1];

        // prefetch eps for this step's phase-B tail (no dependencies)
        float epsv = 0.f;
        size_t oO = (size_t)t * (B * D) + (size_t)bO * D + dO;
        if (tid < 128) epsv = __ldg(eps + oO);

        // ================= phase A: gate GEMMs (K-split) =================
        ull aR[2][4], aZ[2][4], aNx[2][4], aNh[2][4];
        #pragma unroll
        for (int ci = 0; ci < 2; ci++)
            #pragma unroll
            for (int bi = 0; bi < 4; bi++)
                { aR[ci][bi]=0; aZ[ci][bi]=0; aNx[ci][bi]=0; aNh[ci][bi]=0; }

#define PHA_BODY(KP, AN)                                                      \
        {                                                                     \
            int kp = (KP);                                                    \
            ulonglong2 a01 = __ldcg((const ulonglong2*)(actR + kp * B + bq * 4));     \
            ulonglong2 a23 = __ldcg((const ulonglong2*)(actR + kp * B + bq * 4 + 2)); \
            ulonglong2 rz0 = __ldg(wrzB + kp * 8);                            \
            ulonglong2 rz1 = __ldg(wrzB + kp * 8 + 1);                        \
            ulonglong2 nn  = __ldg(wnB  + kp * 4);                            \
            ull av[4] = { a01.x, a01.y, a23.x, a23.y };                       \
            _Pragma("unroll")                                                 \
            for (int bi = 0; bi < 4; bi++) {                                  \
                fma2(aR[0][bi], rz0.x, av[bi]);                               \
                fma2(aZ[0][bi], rz0.y, av[bi]);                               \
                fma2(AN[0][bi], nn.x,  av[bi]);                               \
                fma2(aR[1][bi], rz1.x, av[bi]);                               \
                fma2(aZ[1][bi], rz1.y, av[bi]);                               \
                fma2(AN[1][bi], nn.y,  av[bi]);                               \
            }                                                                 \
        }

        {   // x part: 16 kps per warp
            int kp0 = w * (KPX / NW);
            #pragma unroll 2
            for (int q = 0; q < KPX / NW; q++) PHA_BODY(kp0 + q, aNx)
        }
        {   // h part: 32 kps per warp
            int kp0 = KPX + w * (KPH / NW);
            #pragma unroll 2
            for (int q = 0; q < KPH / NW; q++) PHA_BODY(kp0 + q, aNh)
        }
#undef PHA_BODY

        {   // store partials: idx = ci*16 + bi*4 + g  (conflict-free layout)
            ull* p = smP + (size_t)(w * 32 + lane) * SSTRIDE;
            #pragma unroll
            for (int ci = 0; ci < 2; ci++)
                #pragma unroll
                for (int bi = 0; bi < 4; bi++) {
                    p[ci*16 + bi*4 + 0] = aR [ci][bi];
                    p[ci*16 + bi*4 + 1] = aZ [ci][bi];
                    p[ci*16 + bi*4 + 2] = aNx[ci][bi];
                    p[ci*16 + bi*4 + 3] = aNh[ci][bi];
                }
        }
        __syncthreads();

        if (tid < 256) {   // gating: thread (cG, b) -> h_new[j][b]
            int cG = tid >> 5, b = tid & 31;
            int cgg = cG >> 1, cii = cG & 1, bqq = b >> 2, bii = b & 3;
            int off = cii * 16 + bii * 4;
            ull sR = 0, sZ = 0, sNx = 0, sNh = 0;
            #pragma unroll
            for (int ww = 0; ww < NW; ww++) {
                const ull* p = smP + (size_t)(ww * 32 + cgg * 8 + bqq) * SSTRIDE;
                add2(sR,  p[off + 0]);
                add2(sZ,  p[off + 1]);
                add2(sNx, p[off + 2]);
                add2(sNh, p[off + 3]);
            }
            int j = blk * 8 + cG;
            float2 u;
            u = upk(sR);  float pr  = u.x + u.y + g_bcomb[j];
            u = upk(sZ);  float pz  = u.x + u.y + g_bcomb[H + j];
            u = upk(sNx); float inx = u.x + u.y + g_bcomb[2 * H + j];
            u = upk(sNh); float hnv = u.x + u.y;
            float r = sigmoid_acc(pr);
            float z = sigmoid_acc(pz);
            float n = tanh_acc(fmaf(r, hnv + __ldg(b_n + j), inx));
            int fi = ((KPX + (j >> 1)) * B + b) * 2 + (j & 1);
            float hp = __ldcg((const float*)actR + fi);
            ((float*)actW)[fi] = n + z * (hp - n);
        }
        grid_sync();

        // ================= phase B: decoder + sampling =================
        ull AM[4], AS[4];
        #pragma unroll
        for (int bi = 0; bi < 4; bi++) { AM[bi] = 0; AS[bi] = 0; }
        {
            int kp0 = w * (KPH / NW);
            #pragma unroll 2
            for (int q = 0; q < KPH / NW; q++) {
                int kp = kp0 + q;
                ulonglong2 a01 = __ldcg((const ulonglong2*)(actW + (KPX + kp) * B + bq * 4));
                ulonglong2 a23 = __ldcg((const ulonglong2*)(actW + (KPX + kp) * B + bq * 4 + 2));
                ulonglong2 wv  = __ldg(wdB + kp * 4);
                ull av[4] = { a01.x, a01.y, a23.x, a23.y };
                #pragma unroll
                for (int bi = 0; bi < 4; bi++) {
                    fma2(AM[bi], wv.x, av[bi]);
                    fma2(AS[bi], wv.y, av[bi]);
                }
            }
        }
        __syncthreads();   // smP reuse safe: phase-A readers passed grid_sync
        {   // store partials: idx = m*16 + bi*4 (conflict-free)
            ull* p = smP + (size_t)(w * 32 + lane) * SSTRIDE;
            #pragma unroll
            for (int bi = 0; bi < 4; bi++) {
                p[bi*4]      = AM[bi];
                p[16 + bi*4] = AS[bi];
            }
        }
        __syncthreads();
        if (tid < 128) {
            int bqq = bO >> 2, bii = bO & 3;
            ull sM = 0, sS = 0;
            #pragma unroll
            for (int ww = 0; ww < NW; ww++) {
                const ull* p = smP + (size_t)(ww * 32 + dofO * 8 + bqq) * SSTRIDE;
                add2(sM, p[bii*4]);
                add2(sS, p[16 + bii*4]);
            }
            float2 u;
            u = upk(sM); float mu = u.x + u.y + __ldg(b_dec + dO);
            u = upk(sS); float ls = u.x + u.y + __ldg(b_dec + D + dO);
            float sig = exp_acc(ls);
            float xn = fmaf(sig, epsv, mu);
            ((float*)actW)[(((dO >> 1) * B) + bO) * 2 + (dO & 1)] = xn;
            out[oO]             = xn;
            out[plane + oO]     = mu;
            out[2 * plane + oO] = sig;
        }
        grid_sync();
    }
}

// ---------------- launch ----------------------------------------------------
extern "C" void kernel_launch(void* const* d_in, const int* in_sizes, int n_in,
                              void* d_out, int out_size)
{
    const float* x0    = (const float*)d_in[0];
    const float* eps   = (const float*)d_in[1];
    const float* W_enc = (const float*)d_in[2];
    const float* b_enc = (const float*)d_in[3];
    const float* W_ih  = (const float*)d_in[4];
    const float* W_hh  = (const float*)d_in[5];
    const float* b_gru = (const float*)d_in[6];
    const float* b_n   = (const float*)d_in[7];
    const float* W_dec = (const float*)d_in[8];
    const float* b_dec = (const float*)d_in[9];

    int steps = in_sizes[1] / (B * D);
    float* out = (float*)d_out;

    const int smem_bytes = NTHR * SSTRIDE * sizeof(ull);   // 135168
    cudaFuncSetAttribute(gru_persistent,
                         cudaFuncAttributeMaxDynamicSharedMemorySize, smem_bytes);

    precompute_wcomb<<<H3 / 8, 256>>>(W_ih, W_enc);
    fused_pack<<<NPA + NPD + NPB, 256>>>(W_hh, W_dec, W_ih, b_enc, b_gru);
    init_state<<<(KPH * B + 255) / 256, 256>>>(x0);
    gru_persistent<<<NBLK, NTHR, smem_bytes>>>(b_n, b_dec, eps, out, steps);
}